// round 9
// baseline (speedup 1.0000x reference)
#include <cuda_runtime.h>
#include <cuda_bf16.h>
#include <cstdint>

// CrossPatchModule closed form:
//   out[b,c,h,w] = x[b,c, (m>>3)*64 + (h&63), (m&7)*64 + (w&63)] + ap[c*64+m]
//   with m = (c + (h>>6)*8 + (w>>6)) & 63
//
// Pure permutation gather + scalar add; 512MB irreducible, HBM-bound.
// R8: probe the last point on the (MLP x occupancy) frontier:
//   MLP=6 per thread at 6 CTAs/SM -> 1536 thr/SM * 6 = 9216 in-flight
//   loads per SM (+12.5% over R1's 8192). Front-batched loads, streaming
//   hints, write-linear / read-gather orientation (best measured).
// Chunk 1536 doesn't divide 2^24 -> bounds predicate + per-k c/base.

#define N_F4   16777216u            // 4*64*512*512 / 4
#define CHUNK  1536u                // 256 threads * 6 float4
#define NBLK   10923u               // ceil(N_F4 / CHUNK)

__global__ __launch_bounds__(256, 6)
void crosspatch_kernel(const float4* __restrict__ x,
                       const float*  __restrict__ ap,
                       float4*       __restrict__ out)
{
    unsigned t0 = blockIdx.x * CHUNK + threadIdx.x;

    // bits 0..6 of t are invariant under +k*256
    unsigned w4 = t0 & 127u;
    unsigned pw = w4 >> 4;
    unsigned j4 = w4 & 15u;

    unsigned src[6];
    float    add[6];
    bool     ok[6];

#pragma unroll
    for (int k = 0; k < 6; ++k) {
        unsigned t = t0 + k * 256u;
        ok[k] = (t < N_F4);
        unsigned tc = ok[k] ? t : 0u;          // clamp for safe addr math

        unsigned h    = (tc >> 7) & 511u;
        unsigned c    = (tc >> 16) & 63u;
        unsigned base = (tc >> 16) << 16;      // image base (65536 float4)

        unsigned m  = (c + ((h >> 6) << 3) + pw) & 63u;
        unsigned i  = h & 63u;

        unsigned src_h  = ((m >> 3) << 6) | i;
        unsigned src_w4 = ((m & 7u) << 4) | j4;

        src[k] = base + (src_h << 7) + src_w4;
        add[k] = __ldg(&ap[(c << 6) | m]);
    }

    float4 v[6];
#pragma unroll
    for (int k = 0; k < 6; ++k)
        v[k] = ok[k] ? __ldcs(&x[src[k]]) : make_float4(0.f, 0.f, 0.f, 0.f);

#pragma unroll
    for (int k = 0; k < 6; ++k) {
        if (ok[k]) {
            float a = add[k];
            v[k].x += a; v[k].y += a; v[k].z += a; v[k].w += a;
            __stcs(&out[t0 + k * 256u], v[k]);   // sequential streaming write
        }
    }
}

extern "C" void kernel_launch(void* const* d_in, const int* in_sizes, int n_in,
                              void* d_out, int out_size)
{
    const float4* x   = (const float4*)d_in[0];   // (4,64,512,512) fp32
    const float*  ap  = (const float*)d_in[1];    // (1,1,64,64,1,1) fp32
    float4*       out = (float4*)d_out;

    crosspatch_kernel<<<NBLK, 256>>>(x, ap, out);
}

// round 12
// speedup vs baseline: 1.0055x; 1.0055x over previous
#include <cuda_runtime.h>
#include <cuda_bf16.h>
#include <cstdint>

// CrossPatchModule closed form:
//   B=4, C=64, H=W=512, PH=PW=8, PN=64, kh=kw=64
//   ph=h>>6, i=h&63, pw=w>>6, j=w&63
//   s = ph*8+pw;  m=(c+s)&63
//   out[b,c,h,w] = x[b,c, (m>>3)*64 + i, (m&7)*64 + j] + abs_pos[c*64+m]
//
// FINAL (R7 config): pure permutation gather + scalar add, 512MB irreducible
// traffic, HBM-bound at the measured mixed-R/W ceiling (~6.5 TB/s, 82% DRAM).
// Write-linear / read-gather, MLP=4 front-batched, streaming cache hints,
// k-invariant index math hoisted. Bracketing experiments (MLP 1/4/6/8, both
// orientations, persistent vs waved, occupancy 4/6/8) all converge here.

__global__ __launch_bounds__(256, 8)
void crosspatch_kernel(const float4* __restrict__ x,
                       const float*  __restrict__ ap,
                       float4*       __restrict__ out)
{
    // 4 float4 per thread at stride 256 float4: each warp access is 32
    // consecutive float4 (512B), fully coalesced on both sides.
    unsigned t0 = blockIdx.x * 1024u + threadIdx.x;

    // k-invariant pieces: t0 + k*256 leaves bits 0..6 unchanged, and a
    // 1024-float4 block chunk never straddles an image (65536 % 1024 == 0),
    // so c and base are constant across the 4 elements.
    unsigned w4 = t0 & 127u;
    unsigned pw = w4 >> 4;
    unsigned j4 = w4 & 15u;
    unsigned c  = (t0 >> 16) & 63u;
    unsigned base = (t0 >> 16) << 16;          // ((b*64+c) image) * 65536

    unsigned src[4];
    float    add[4];

#pragma unroll
    for (int k = 0; k < 4; ++k) {
        unsigned h  = ((t0 + k * 256u) >> 7) & 511u;
        unsigned ph = h >> 6;
        unsigned i  = h & 63u;

        unsigned m  = (c + ph * 8u + pw) & 63u;
        unsigned src_h  = ((m >> 3) << 6) | i;
        unsigned src_w4 = ((m & 7u) << 4) | j4;

        src[k] = base + (src_h << 7) + src_w4;
        add[k] = __ldg(&ap[(c << 6) | m]);
    }

    float4 v[4];
#pragma unroll
    for (int k = 0; k < 4; ++k)
        v[k] = __ldcs(&x[src[k]]);             // streaming gather (no reuse)

#pragma unroll
    for (int k = 0; k < 4; ++k) {
        float a = add[k];
        v[k].x += a; v[k].y += a; v[k].z += a; v[k].w += a;
        __stcs(&out[t0 + k * 256u], v[k]);     // sequential streaming write
    }
}

extern "C" void kernel_launch(void* const* d_in, const int* in_sizes, int n_in,
                              void* d_out, int out_size)
{
    const float4* x   = (const float4*)d_in[0];   // (4,64,512,512) fp32
    const float*  ap  = (const float*)d_in[1];    // (1,1,64,64,1,1) fp32
    float4*       out = (float4*)d_out;

    crosspatch_kernel<<<16384, 256>>>(x, ap, out);
}